// round 13
// baseline (speedup 1.0000x reference)
#include <cuda_runtime.h>
#include <cuda_fp16.h>
#include <cstdint>

// ---------------- problem geometry ----------------
#define M_TOTAL 256
#define K_CONV  2304          // 256*3*3
#define IN_HW   56
#define IN_PLANE 3136
#define IN_CHW  802816        // 256*56*56
#define NX      25690112      // 32*802816 elements of x
#define OUT_HW  54
#define IMG_PIX 2916

// ---------------- GEMM tiling ----------------
#define BM 128
#define BN 128
#define BK 64
#define KITERS 36             // 2304/64
#define KQ_TOTAL 144          // 2304/16 k16-groups
#define JT_PER_IMG 24         // 3072/128

#define B_ROW_B 272           // (128+8) halves * 2B
#define B_STAGE (BK * B_ROW_B)            // 17408 B
#define NSTAGES 5
#define DYN_SMEM (NSTAGES * B_STAGE)      // 87040 B

// ---------------- device scratch ----------------
// A in mma fragment layout: [q (k16 group)][G (m16 group)][lane] -> uint4
__device__ uint4 g_Af[KQ_TOTAL * 16 * 32];
__device__ __half g_xh[3][NX + 4096];             // fp16(x) shifted by 0,1,2
__device__ unsigned long long g_rowptr[K_CONV];   // per-k base ptr into g_xh

// ---------------- helpers ----------------
__device__ __forceinline__ uint32_t smem_u32(const void* p) {
    uint32_t a;
    asm("{ .reg .u64 t; cvta.to.shared.u64 t, %1; cvt.u32.u64 %0, t; }" : "=r"(a) : "l"(p));
    return a;
}
__device__ __forceinline__ void cpa16(uint32_t dst, const void* src) {
    asm volatile("cp.async.cg.shared.global [%0], [%1], 16;" :: "r"(dst), "l"(src));
}

// ---------------- prep: A fragments + rowptr (merged) ----------------
__device__ __forceinline__ unsigned short sign_h(const float* w, int oc, int k) {
    float v = w[oc * K_CONV + k];
    return (v > 0.0f) ? 0x3C00u : ((v < 0.0f) ? 0xBC00u : 0u);
}

__global__ void afrag_kernel(const float* __restrict__ w) {
    int idx = blockIdx.x * blockDim.x + threadIdx.x;
    if (idx < K_CONV) {
        int k = idx;
        int c  = k / 9;
        int r9 = k - c * 9;
        int kh = r9 / 3;
        int kw = r9 - kh * 3;
        g_rowptr[k] = (unsigned long long)(g_xh[kw] + c * IN_PLANE + kh * IN_HW);
    }
    if (idx >= KQ_TOTAL * 16 * 32) return;
    int lane = idx & 31;
    int G    = (idx >> 5) & 15;
    int q    = idx >> 9;

    int r_lo = G * 16 + (lane >> 2);
    int r_hi = r_lo + 8;
    int c_lo = q * 16 + (lane & 3) * 2;
    int c_hi = c_lo + 8;

    uint32_t v0 = (uint32_t)sign_h(w, r_lo, c_lo) | ((uint32_t)sign_h(w, r_lo, c_lo + 1) << 16);
    uint32_t v1 = (uint32_t)sign_h(w, r_hi, c_lo) | ((uint32_t)sign_h(w, r_hi, c_lo + 1) << 16);
    uint32_t v2 = (uint32_t)sign_h(w, r_lo, c_hi) | ((uint32_t)sign_h(w, r_lo, c_hi + 1) << 16);
    uint32_t v3 = (uint32_t)sign_h(w, r_hi, c_hi) | ((uint32_t)sign_h(w, r_hi, c_hi + 1) << 16);
    g_Af[idx] = make_uint4(v0, v1, v2, v3);
}

__global__ void split_kernel(const float* __restrict__ x) {
    long i0 = ((long)blockIdx.x * blockDim.x + threadIdx.x) * 8;
    if (i0 >= NX) return;

    float v[10];
    if (i0 + 12 <= NX) {
        float4 a = *reinterpret_cast<const float4*>(x + i0);
        float4 b = *reinterpret_cast<const float4*>(x + i0 + 4);
        float4 c = *reinterpret_cast<const float4*>(x + i0 + 8);
        v[0]=a.x; v[1]=a.y; v[2]=a.z; v[3]=a.w;
        v[4]=b.x; v[5]=b.y; v[6]=b.z; v[7]=b.w;
        v[8]=c.x; v[9]=c.y;
    } else {
#pragma unroll
        for (int t = 0; t < 10; t++) v[t] = (i0 + t < NX) ? x[i0 + t] : 0.0f;
    }

    uint32_t hp[5], hq[4];
#pragma unroll
    for (int j = 0; j < 5; j++) {
        __half2 h = __floats2half2_rn(v[2*j], v[2*j+1]);
        hp[j] = *reinterpret_cast<uint32_t*>(&h);
    }
#pragma unroll
    for (int j = 0; j < 4; j++) {
        __half2 h = __floats2half2_rn(v[2*j+1], v[2*j+2]);
        hq[j] = *reinterpret_cast<uint32_t*>(&h);
    }

    *reinterpret_cast<uint4*>(&g_xh[0][i0]) = make_uint4(hp[0], hp[1], hp[2], hp[3]);
    *reinterpret_cast<uint4*>(&g_xh[1][i0]) = make_uint4(hq[0], hq[1], hq[2], hq[3]);
    *reinterpret_cast<uint4*>(&g_xh[2][i0]) = make_uint4(hp[1], hp[2], hp[3], hp[4]);
}

// ---------------- GEMM ----------------
extern __shared__ char smem_raw[];

__global__ void __launch_bounds__(256, 2)
bconv_mma(float* __restrict__ out) {
    const int tid = threadIdx.x;
    const int lane = tid & 31;
    const int wid = tid >> 5;
    const int warp_m = wid >> 1;     // 4 M-warps (32 rows each)
    const int warp_n = wid & 1;      // 2 N-warps (64 cols each)
    const int m0 = blockIdx.x * BM;
    const int by = blockIdx.y;
    const int b  = by / JT_PER_IMG;
    const int j0 = (by - b * JT_PER_IMG) * BN;
    const long img_off = (long)b * IN_CHW + j0;

    char* sm = smem_raw;

    const int G_base = (m0 >> 4) + warp_m * 2;
    const uint4* afp = g_Af + lane;   // + (q*16+G)*32

    const uint32_t b_lds_off = (uint32_t)((lane & 15) * B_ROW_B
                                          + (warp_n * 64 + ((lane >> 4) << 3)) * 2);

    float acc[2][8][4];
#pragma unroll
    for (int mi = 0; mi < 2; mi++)
#pragma unroll
        for (int ni = 0; ni < 8; ni++)
#pragma unroll
            for (int e = 0; e < 4; e++) acc[mi][ni][e] = 0.0f;

    const int b_rowq = tid >> 4, b_col = tid & 15;

    // one 16-row chunk of a stage (i = 0..3)
    auto load_chunk = [&](int kblk, int st, int i) {
        uint32_t bbase = smem_u32(sm + st * B_STAGE);
        int kr = b_rowq + i * 16;
        const __half* src = (const __half*)g_rowptr[kblk * BK + kr] + img_off + b_col * 8;
        cpa16(bbase + kr * B_ROW_B + b_col * 16, src);
    };
    auto load_stage = [&](int kblk, int st) {
#pragma unroll
        for (int i = 0; i < 4; i++) load_chunk(kblk, st, i);
    };

    load_stage(0, 0); asm volatile("cp.async.commit_group;");
    load_stage(1, 1); asm volatile("cp.async.commit_group;");
    load_stage(2, 2); asm volatile("cp.async.commit_group;");
    load_stage(3, 3); asm volatile("cp.async.commit_group;");

    uint4 af[2][2];           // [buf][mi]
    uint32_t bf[2][8][2];     // [buf][ni][2]

    auto a_load = [&](int buf, int q) {
#pragma unroll
        for (int mi = 0; mi < 2; mi++)
            af[buf][mi] = afp[(size_t)(q * 16 + G_base + mi) * 32];
    };
    auto b_load = [&](int buf, uint32_t bbase, int kk) {
#pragma unroll
        for (int g = 0; g < 4; g++) {
            uint32_t addr = bbase + (uint32_t)(kk * 16 * B_ROW_B + g * 32) + b_lds_off;
            asm volatile("ldmatrix.sync.aligned.m8n8.x4.trans.shared.b16 {%0,%1,%2,%3}, [%4];"
                         : "=r"(bf[buf][2*g][0]), "=r"(bf[buf][2*g][1]),
                           "=r"(bf[buf][2*g+1][0]), "=r"(bf[buf][2*g+1][1])
                         : "r"(addr));
        }
    };

#pragma unroll 1
    for (int it = 0; it < KITERS; it++) {
        // 4 groups in flight; wait 3 -> stage it complete (newest 3 pending)
        asm volatile("cp.async.wait_group 3;" ::: "memory");
        __syncthreads();

        uint32_t bbase = smem_u32(sm + (it % NSTAGES) * B_STAGE);
        const int q0 = it * 4;
        const bool more = (it + 4 < KITERS);
        const int nst = (it + 4) % NSTAGES;

        // kk0 fragments from the just-arrived stage
        a_load(0, q0);
        b_load(0, bbase, 0);

#pragma unroll
        for (int kk = 0; kk < 4; kk++) {
            const int cur = kk & 1, nxt = cur ^ 1;
            // spread next-stage cp.async: one 16-row chunk per kk
            if (more) load_chunk(it + 4, nst, kk);
            if (kk == 3) asm volatile("cp.async.commit_group;");
            if (kk < 3) {
                a_load(nxt, q0 + kk + 1);
                b_load(nxt, bbase, kk + 1);
            }
#pragma unroll
            for (int mi = 0; mi < 2; mi++)
#pragma unroll
                for (int ni = 0; ni < 8; ni++) {
                    asm volatile(
                        "mma.sync.aligned.m16n8k16.row.col.f32.f16.f16.f32 "
                        "{%0,%1,%2,%3}, {%4,%5,%6,%7}, {%8,%9}, {%0,%1,%2,%3};"
                        : "+f"(acc[mi][ni][0]), "+f"(acc[mi][ni][1]),
                          "+f"(acc[mi][ni][2]), "+f"(acc[mi][ni][3])
                        : "r"(af[cur][mi].x), "r"(af[cur][mi].y),
                          "r"(af[cur][mi].z), "r"(af[cur][mi].w),
                          "r"(bf[cur][ni][0]), "r"(bf[cur][ni][1]));
                }
        }
        if (!more) asm volatile("cp.async.commit_group;");  // keep group count uniform
    }

    // ---- epilogue: paired float2 stores ----
#pragma unroll
    for (int mi = 0; mi < 2; mi++) {
        int m_lo = m0 + warp_m * 32 + mi * 16 + (lane >> 2);
#pragma unroll
        for (int ni = 0; ni < 8; ni++) {
            int jb = j0 + warp_n * 64 + ni * 8 + (lane & 3) * 2;   // even
            int oh = jb / IN_HW;
            int ow = jb - oh * IN_HW;
            if (oh < OUT_HW && ow < OUT_HW) {
#pragma unroll
                for (int h = 0; h < 2; h++) {                       // row r, r+8
                    int mm = m_lo + h * 8;
                    float* dst = out + ((size_t)(b * M_TOTAL + mm)) * IMG_PIX + oh * OUT_HW + ow;
                    if (ow + 1 < OUT_HW) {
                        *reinterpret_cast<float2*>(dst) =
                            make_float2(acc[mi][ni][2*h], acc[mi][ni][2*h + 1]);
                    } else {
                        *dst = acc[mi][ni][2*h];
                    }
                }
            }
        }
    }
}

// ---------------- launcher ----------------
extern "C" void kernel_launch(void* const* d_in, const int* in_sizes, int n_in,
                              void* d_out, int out_size) {
    (void)in_sizes; (void)n_in; (void)out_size;
    const float* x = (const float*)d_in[0];
    const float* w = (const float*)d_in[1];
    float* out = (float*)d_out;

    afrag_kernel<<<(KQ_TOTAL * 16 * 32 + 255) / 256, 256>>>(w);
    split_kernel<<<(int)((NX / 8 + 255) / 256), 256>>>(x);

    cudaFuncSetAttribute(bconv_mma, cudaFuncAttributeMaxDynamicSharedMemorySize, DYN_SMEM);
    dim3 grid(M_TOTAL / BM, 32 * JT_PER_IMG);   // (2, 768)
    bconv_mma<<<grid, 256, DYN_SMEM>>>(out);
}

// round 14
// speedup vs baseline: 1.0133x; 1.0133x over previous
#include <cuda_runtime.h>
#include <cuda_fp16.h>
#include <cstdint>

// ---------------- problem geometry ----------------
#define M_TOTAL 256
#define K_CONV  2304          // 256*3*3
#define IN_HW   56
#define IN_PLANE 3136
#define IN_CHW  802816        // 256*56*56
#define NX      25690112      // 32*802816 elements of x
#define OUT_HW  54
#define IMG_PIX 2916

// ---------------- GEMM tiling ----------------
#define BM 128
#define BN 128
#define BK 64
#define KITERS 36             // 2304/64
#define KQ_TOTAL 144          // 2304/16 k16-groups
#define JT_PER_IMG 24         // 3072/128

#define B_ROW_B 272           // (128+8) halves * 2B
#define B_STAGE (BK * B_ROW_B)            // 17408 B
#define NSTAGES 4
#define DYN_SMEM (NSTAGES * B_STAGE)      // 69632 B

// ---------------- device scratch ----------------
// A in mma fragment layout: [q (k16 group)][G (m16 group)][lane] -> uint4
__device__ uint4 g_Af[KQ_TOTAL * 16 * 32];
__device__ __half g_xh[3][NX + 4096];             // fp16(x) shifted by 0,1,2
__device__ unsigned long long g_rowptr[K_CONV];   // per-k base ptr into g_xh

// ---------------- helpers ----------------
__device__ __forceinline__ uint32_t smem_u32(const void* p) {
    uint32_t a;
    asm("{ .reg .u64 t; cvta.to.shared.u64 t, %1; cvt.u32.u64 %0, t; }" : "=r"(a) : "l"(p));
    return a;
}
__device__ __forceinline__ void cpa16(uint32_t dst, const void* src) {
    asm volatile("cp.async.cg.shared.global [%0], [%1], 16;" :: "r"(dst), "l"(src));
}

// ---------------- prep: A fragments + rowptr (merged) ----------------
__device__ __forceinline__ unsigned short sign_h(const float* w, int oc, int k) {
    float v = w[oc * K_CONV + k];
    return (v > 0.0f) ? 0x3C00u : ((v < 0.0f) ? 0xBC00u : 0u);
}

__global__ void afrag_kernel(const float* __restrict__ w) {
    int idx = blockIdx.x * blockDim.x + threadIdx.x;
    if (idx < K_CONV) {
        int k = idx;
        int c  = k / 9;
        int r9 = k - c * 9;
        int kh = r9 / 3;
        int kw = r9 - kh * 3;
        g_rowptr[k] = (unsigned long long)(g_xh[kw] + c * IN_PLANE + kh * IN_HW);
    }
    if (idx >= KQ_TOTAL * 16 * 32) return;
    int lane = idx & 31;
    int G    = (idx >> 5) & 15;
    int q    = idx >> 9;

    int r_lo = G * 16 + (lane >> 2);
    int r_hi = r_lo + 8;
    int c_lo = q * 16 + (lane & 3) * 2;
    int c_hi = c_lo + 8;

    uint32_t v0 = (uint32_t)sign_h(w, r_lo, c_lo) | ((uint32_t)sign_h(w, r_lo, c_lo + 1) << 16);
    uint32_t v1 = (uint32_t)sign_h(w, r_hi, c_lo) | ((uint32_t)sign_h(w, r_hi, c_lo + 1) << 16);
    uint32_t v2 = (uint32_t)sign_h(w, r_lo, c_hi) | ((uint32_t)sign_h(w, r_lo, c_hi + 1) << 16);
    uint32_t v3 = (uint32_t)sign_h(w, r_hi, c_hi) | ((uint32_t)sign_h(w, r_hi, c_hi + 1) << 16);
    g_Af[idx] = make_uint4(v0, v1, v2, v3);
}

__global__ void split_kernel(const float* __restrict__ x) {
    long i0 = ((long)blockIdx.x * blockDim.x + threadIdx.x) * 8;
    if (i0 >= NX) return;

    float v[10];
    if (i0 + 12 <= NX) {
        float4 a = *reinterpret_cast<const float4*>(x + i0);
        float4 b = *reinterpret_cast<const float4*>(x + i0 + 4);
        float4 c = *reinterpret_cast<const float4*>(x + i0 + 8);
        v[0]=a.x; v[1]=a.y; v[2]=a.z; v[3]=a.w;
        v[4]=b.x; v[5]=b.y; v[6]=b.z; v[7]=b.w;
        v[8]=c.x; v[9]=c.y;
    } else {
#pragma unroll
        for (int t = 0; t < 10; t++) v[t] = (i0 + t < NX) ? x[i0 + t] : 0.0f;
    }

    uint32_t hp[5], hq[4];
#pragma unroll
    for (int j = 0; j < 5; j++) {
        __half2 h = __floats2half2_rn(v[2*j], v[2*j+1]);
        hp[j] = *reinterpret_cast<uint32_t*>(&h);
    }
#pragma unroll
    for (int j = 0; j < 4; j++) {
        __half2 h = __floats2half2_rn(v[2*j+1], v[2*j+2]);
        hq[j] = *reinterpret_cast<uint32_t*>(&h);
    }

    *reinterpret_cast<uint4*>(&g_xh[0][i0]) = make_uint4(hp[0], hp[1], hp[2], hp[3]);
    *reinterpret_cast<uint4*>(&g_xh[1][i0]) = make_uint4(hq[0], hq[1], hq[2], hq[3]);
    *reinterpret_cast<uint4*>(&g_xh[2][i0]) = make_uint4(hp[1], hp[2], hp[3], hp[4]);
}

// ---------------- GEMM ----------------
extern __shared__ char smem_raw[];

__global__ void __launch_bounds__(256, 2)
bconv_mma(float* __restrict__ out) {
    const int tid = threadIdx.x;
    const int lane = tid & 31;
    const int wid = tid >> 5;
    const int warp_m = wid >> 1;     // 4 M-warps (32 rows each)
    const int warp_n = wid & 1;      // 2 N-warps (64 cols each)
    const int m0 = blockIdx.x * BM;
    const int by = blockIdx.y;
    const int b  = by / JT_PER_IMG;
    const int j0 = (by - b * JT_PER_IMG) * BN;
    const long img_off = (long)b * IN_CHW + j0;

    char* sm = smem_raw;

    const int G_base = (m0 >> 4) + warp_m * 2;
    const uint4* afp = g_Af + lane;   // + (q*16+G)*32

    const uint32_t b_lds_off = (uint32_t)((lane & 15) * B_ROW_B
                                          + (warp_n * 64 + ((lane >> 4) << 3)) * 2);

    float acc[2][8][4];
#pragma unroll
    for (int mi = 0; mi < 2; mi++)
#pragma unroll
        for (int ni = 0; ni < 8; ni++)
#pragma unroll
            for (int e = 0; e < 4; e++) acc[mi][ni][e] = 0.0f;

    const int b_rowq = tid >> 4, b_col = tid & 15;

    // one 16-row chunk of a stage (i = 0..3)
    auto load_chunk = [&](int kblk, int st, int i) {
        uint32_t bbase = smem_u32(sm + st * B_STAGE);
        int kr = b_rowq + i * 16;
        const __half* src = (const __half*)g_rowptr[kblk * BK + kr] + img_off + b_col * 8;
        cpa16(bbase + kr * B_ROW_B + b_col * 16, src);
    };
    auto load_stage = [&](int kblk, int st) {
#pragma unroll
        for (int i = 0; i < 4; i++) load_chunk(kblk, st, i);
    };

    load_stage(0, 0); asm volatile("cp.async.commit_group;");
    load_stage(1, 1); asm volatile("cp.async.commit_group;");
    load_stage(2, 2); asm volatile("cp.async.commit_group;");

    uint4 af[2][2];           // [buf][mi]
    uint32_t bf[2][8][2];     // [buf][ni][2]

    auto a_load = [&](int buf, int q) {
#pragma unroll
        for (int mi = 0; mi < 2; mi++)
            af[buf][mi] = afp[(size_t)(q * 16 + G_base + mi) * 32];
    };
    auto b_load = [&](int buf, uint32_t bbase, int kk) {
#pragma unroll
        for (int g = 0; g < 4; g++) {
            uint32_t addr = bbase + (uint32_t)(kk * 16 * B_ROW_B + g * 32) + b_lds_off;
            asm volatile("ldmatrix.sync.aligned.m8n8.x4.trans.shared.b16 {%0,%1,%2,%3}, [%4];"
                         : "=r"(bf[buf][2*g][0]), "=r"(bf[buf][2*g][1]),
                           "=r"(bf[buf][2*g+1][0]), "=r"(bf[buf][2*g+1][1])
                         : "r"(addr));
        }
    };

#pragma unroll 1
    for (int it = 0; it < KITERS; it++) {
        asm volatile("cp.async.wait_group 2;" ::: "memory");
        __syncthreads();

        uint32_t bbase = smem_u32(sm + (it & 3) * B_STAGE);
        const int q0 = it * 4;
        const bool more = (it + 3 < KITERS);
        const int nst = (it + 3) & 3;

        // kk0 fragments from the just-arrived stage
        a_load(0, q0);
        b_load(0, bbase, 0);

#pragma unroll
        for (int kk = 0; kk < 4; kk++) {
            const int cur = kk & 1, nxt = cur ^ 1;
            // spread next-stage cp.async: one 16-row chunk per kk
            if (more) load_chunk(it + 3, nst, kk);
            if (kk == 3) asm volatile("cp.async.commit_group;");
            if (kk < 3) {
                a_load(nxt, q0 + kk + 1);
                b_load(nxt, bbase, kk + 1);
            }
#pragma unroll
            for (int mi = 0; mi < 2; mi++)
#pragma unroll
                for (int ni = 0; ni < 8; ni++) {
                    asm volatile(
                        "mma.sync.aligned.m16n8k16.row.col.f32.f16.f16.f32 "
                        "{%0,%1,%2,%3}, {%4,%5,%6,%7}, {%8,%9}, {%0,%1,%2,%3};"
                        : "+f"(acc[mi][ni][0]), "+f"(acc[mi][ni][1]),
                          "+f"(acc[mi][ni][2]), "+f"(acc[mi][ni][3])
                        : "r"(af[cur][mi].x), "r"(af[cur][mi].y),
                          "r"(af[cur][mi].z), "r"(af[cur][mi].w),
                          "r"(bf[cur][ni][0]), "r"(bf[cur][ni][1]));
                }
        }
        if (!more) asm volatile("cp.async.commit_group;");  // keep group count uniform
    }

    // ---- epilogue: paired float2 stores ----
#pragma unroll
    for (int mi = 0; mi < 2; mi++) {
        int m_lo = m0 + warp_m * 32 + mi * 16 + (lane >> 2);
#pragma unroll
        for (int ni = 0; ni < 8; ni++) {
            int jb = j0 + warp_n * 64 + ni * 8 + (lane & 3) * 2;   // even
            int oh = jb / IN_HW;
            int ow = jb - oh * IN_HW;
            if (oh < OUT_HW && ow < OUT_HW) {
#pragma unroll
                for (int h = 0; h < 2; h++) {                       // row r, r+8
                    int mm = m_lo + h * 8;
                    float* dst = out + ((size_t)(b * M_TOTAL + mm)) * IMG_PIX + oh * OUT_HW + ow;
                    if (ow + 1 < OUT_HW) {
                        *reinterpret_cast<float2*>(dst) =
                            make_float2(acc[mi][ni][2*h], acc[mi][ni][2*h + 1]);
                    } else {
                        *dst = acc[mi][ni][2*h];
                    }
                }
            }
        }
    }
}

// ---------------- launcher ----------------
extern "C" void kernel_launch(void* const* d_in, const int* in_sizes, int n_in,
                              void* d_out, int out_size) {
    (void)in_sizes; (void)n_in; (void)out_size;
    const float* x = (const float*)d_in[0];
    const float* w = (const float*)d_in[1];
    float* out = (float*)d_out;

    afrag_kernel<<<(KQ_TOTAL * 16 * 32 + 255) / 256, 256>>>(w);
    split_kernel<<<(int)((NX / 8 + 255) / 256), 256>>>(x);

    cudaFuncSetAttribute(bconv_mma, cudaFuncAttributeMaxDynamicSharedMemorySize, DYN_SMEM);
    dim3 grid(M_TOTAL / BM, 32 * JT_PER_IMG);   // (2, 768)
    bconv_mma<<<grid, 256, DYN_SMEM>>>(out);
}